// round 12
// baseline (speedup 1.0000x reference)
#include <cuda_runtime.h>
#include <math.h>

#define MAX_N 100000
#define MAX_E 1600000
#define D 64
#define TWO_D 128
#define NB 64
#define SCAN_B 512
#define MAXNB ((MAX_N + SCAN_B - 1) / SCAN_B)   // 196

// Scratch (static __device__ arrays — no allocations allowed)
__device__ float4 g_srcv[MAX_N];                 // (low_src, high_src, dnorm, 0)
__device__ float4 g_dstv[MAX_N];                 // (low_dst, high_dst, dnorm, 0)
__device__ float  g_z[(size_t)MAX_N * TWO_D];    // [N, 2D] aggregation
__device__ float  g_WrT[TWO_D * D];              // Wr transposed [k][j]
__device__ int    g_deg[MAX_N];
__device__ int    g_start[MAX_N];
__device__ int    g_cursor[MAX_N];
__device__ int    g_bsum[MAXNB + 1];
__device__ int    g_esrc[MAX_E];                 // dst-grouped src indices

// ---------------------------------------------------------------------------
// Gate projections: one warp per node. Fused: Wr transpose + deg zero.
// ---------------------------------------------------------------------------
__global__ void gate_kernel(const float* __restrict__ h,
                            const float* __restrict__ dnorm,
                            const float* __restrict__ Wl,
                            const float* __restrict__ Wh,
                            const float* __restrict__ Wr,
                            int n)
{
    int gtid = blockIdx.x * blockDim.x + threadIdx.x;

    if (gtid < D * TWO_D) {
        int j = gtid >> 7;
        int k = gtid & 127;
        g_WrT[k * D + j] = Wr[gtid];
    }
    if (gtid < n) g_deg[gtid] = 0;

    int warp = gtid >> 5;
    int lane = threadIdx.x & 31;
    if (warp >= n) return;

    const float* hp = h + (size_t)warp * D;
    float a0 = hp[lane];
    float a1 = hp[lane + 32];

    float ld = a0 * Wl[lane]      + a1 * Wl[lane + 32];
    float ls = a0 * Wl[lane + 64] + a1 * Wl[lane + 96];
    float hd = a0 * Wh[lane]      + a1 * Wh[lane + 32];
    float hs = a0 * Wh[lane + 64] + a1 * Wh[lane + 96];

    #pragma unroll
    for (int off = 16; off; off >>= 1) {
        ld += __shfl_xor_sync(0xFFFFFFFFu, ld, off);
        ls += __shfl_xor_sync(0xFFFFFFFFu, ls, off);
        hd += __shfl_xor_sync(0xFFFFFFFFu, hd, off);
        hs += __shfl_xor_sync(0xFFFFFFFFu, hs, off);
    }
    if (lane == 0) {
        float dn = dnorm[warp];
        g_srcv[warp] = make_float4(ls, hs, dn, 0.f);
        g_dstv[warp] = make_float4(ld, hd, dn, 0.f);
    }
}

// ---------------------------------------------------------------------------
__global__ void hist_kernel(const int* __restrict__ dst, int e)
{
    int i = blockIdx.x * blockDim.x + threadIdx.x;
    int e4 = e >> 2;
    if (i < e4) {
        int4 d4 = reinterpret_cast<const int4*>(dst)[i];
        atomicAdd(&g_deg[d4.x], 1);
        atomicAdd(&g_deg[d4.y], 1);
        atomicAdd(&g_deg[d4.z], 1);
        atomicAdd(&g_deg[d4.w], 1);
    }
    int t = e4 * 4 + i;
    if (i < (e & 3)) {
        atomicAdd(&g_deg[dst[t]], 1);
    }
}

// ---------------------------------------------------------------------------
__global__ void scan1_kernel(int n)
{
    __shared__ int swarp[16];
    int tid  = threadIdx.x;
    int lane = tid & 31;
    int wid  = tid >> 5;
    int i = blockIdx.x * SCAN_B + tid;
    int v = (i < n) ? g_deg[i] : 0;

    int x = v;
    #pragma unroll
    for (int off = 1; off < 32; off <<= 1) {
        int t = __shfl_up_sync(0xFFFFFFFFu, x, off);
        if (lane >= off) x += t;
    }
    if (lane == 31) swarp[wid] = x;
    __syncthreads();

    if (wid == 0) {
        int w = (lane < 16) ? swarp[lane] : 0;
        #pragma unroll
        for (int off = 1; off < 16; off <<= 1) {
            int t = __shfl_up_sync(0xFFFFFFFFu, w, off);
            if (lane >= off) w += t;
        }
        if (lane < 16) swarp[lane] = w;
    }
    __syncthreads();

    int wbase = (wid > 0) ? swarp[wid - 1] : 0;
    if (i < n) g_start[i] = wbase + x - v;
    if (tid == SCAN_B - 1) g_bsum[blockIdx.x] = wbase + x;
}

// ---------------------------------------------------------------------------
__global__ void scan3_kernel(int n, int nb)
{
    __shared__ int sb[MAXNB];
    __shared__ int swarp[8];
    int tid  = threadIdx.x;
    int lane = tid & 31;
    int wid  = tid >> 5;

    int v = (tid < nb) ? g_bsum[tid] : 0;
    int x = v;
    #pragma unroll
    for (int off = 1; off < 32; off <<= 1) {
        int t = __shfl_up_sync(0xFFFFFFFFu, x, off);
        if (lane >= off) x += t;
    }
    if (lane == 31) swarp[wid] = x;
    __syncthreads();
    if (wid == 0) {
        int w = (lane < 8) ? swarp[lane] : 0;
        #pragma unroll
        for (int off = 1; off < 8; off <<= 1) {
            int t = __shfl_up_sync(0xFFFFFFFFu, w, off);
            if (lane >= off) w += t;
        }
        if (lane < 8) swarp[lane] = w;
    }
    __syncthreads();
    int wbase = (wid > 0) ? swarp[wid - 1] : 0;
    if (tid < nb) sb[tid] = wbase + x - v;
    __syncthreads();

    int i = blockIdx.x * blockDim.x + tid;
    if (i < n) {
        int s = g_start[i] + sb[i / SCAN_B];
        g_start[i] = s;
        g_cursor[i] = s;
    }
}

// ---------------------------------------------------------------------------
__global__ void fill_kernel(const int* __restrict__ src,
                            const int* __restrict__ dst,
                            int e)
{
    int i = blockIdx.x * blockDim.x + threadIdx.x;
    if (i >= e) return;
    int pos = atomicAdd(&g_cursor[dst[i]], 1);
    g_esrc[pos] = src[i];
}

// ---------------------------------------------------------------------------
// Gather-aggregate: one warp per node, strided lanes, UNROLL 8 (flat scalars).
// ---------------------------------------------------------------------------
__global__ void gather_kernel(const float* __restrict__ h,
                              const float* __restrict__ bl,
                              const float* __restrict__ bh,
                              int n)
{
    int warp = (blockIdx.x * blockDim.x + threadIdx.x) >> 5;
    int lane = threadIdx.x & 31;
    if (warp >= n) return;

    int start = g_start[warp];
    int deg   = g_deg[warp];
    int end   = start + deg;

    float4 dv  = g_dstv[warp];
    float xl_base = dv.x + bl[0];
    float xh_base = dv.y + bh[0];
    float dn_t = dv.z;

    float zl0 = 0.f, zl1 = 0.f, zh0 = 0.f, zh1 = 0.f;

    for (int base = start; base < end; base += 32) {
        int my = base + lane;
        int msrc = 0;
        float mel = 0.f, meh = 0.f;
        if (my < end) {
            msrc = g_esrc[my];
            float4 sv = g_srcv[msrc];
            float xl = xl_base + sv.x;
            float xh = xh_base + sv.y;
            float gl =  tanhf(xl > 0.f ? xl : -0.5f * xl);
            float gh = -tanhf(xh > 0.f ? xh : -0.5f * xh);
            float dd = dn_t * sv.z;
            mel = gl * dd;
            meh = gh * dd;
        }
        int cnt = min(32, end - base);

        int i = 0;
        for (; i + 8 <= cnt; i += 8) {
            int s0 = __shfl_sync(0xFFFFFFFFu, msrc, i);
            int s1 = __shfl_sync(0xFFFFFFFFu, msrc, i + 1);
            int s2 = __shfl_sync(0xFFFFFFFFu, msrc, i + 2);
            int s3 = __shfl_sync(0xFFFFFFFFu, msrc, i + 3);
            int s4 = __shfl_sync(0xFFFFFFFFu, msrc, i + 4);
            int s5 = __shfl_sync(0xFFFFFFFFu, msrc, i + 5);
            int s6 = __shfl_sync(0xFFFFFFFFu, msrc, i + 6);
            int s7 = __shfl_sync(0xFFFFFFFFu, msrc, i + 7);

            const float* p0 = h + (size_t)s0 * D;
            const float* p1 = h + (size_t)s1 * D;
            const float* p2 = h + (size_t)s2 * D;
            const float* p3 = h + (size_t)s3 * D;
            const float* p4 = h + (size_t)s4 * D;
            const float* p5 = h + (size_t)s5 * D;
            const float* p6 = h + (size_t)s6 * D;
            const float* p7 = h + (size_t)s7 * D;
            float a0 = p0[lane], b0 = p0[lane + 32];
            float a1 = p1[lane], b1 = p1[lane + 32];
            float a2 = p2[lane], b2 = p2[lane + 32];
            float a3 = p3[lane], b3 = p3[lane + 32];
            float a4 = p4[lane], b4 = p4[lane + 32];
            float a5 = p5[lane], b5 = p5[lane + 32];
            float a6 = p6[lane], b6 = p6[lane + 32];
            float a7 = p7[lane], b7 = p7[lane + 32];

            float cl0 = __shfl_sync(0xFFFFFFFFu, mel, i);
            float ch0 = __shfl_sync(0xFFFFFFFFu, meh, i);
            float cl1 = __shfl_sync(0xFFFFFFFFu, mel, i + 1);
            float ch1 = __shfl_sync(0xFFFFFFFFu, meh, i + 1);
            float cl2 = __shfl_sync(0xFFFFFFFFu, mel, i + 2);
            float ch2 = __shfl_sync(0xFFFFFFFFu, meh, i + 2);
            float cl3 = __shfl_sync(0xFFFFFFFFu, mel, i + 3);
            float ch3 = __shfl_sync(0xFFFFFFFFu, meh, i + 3);
            float cl4 = __shfl_sync(0xFFFFFFFFu, mel, i + 4);
            float ch4 = __shfl_sync(0xFFFFFFFFu, meh, i + 4);
            float cl5 = __shfl_sync(0xFFFFFFFFu, mel, i + 5);
            float ch5 = __shfl_sync(0xFFFFFFFFu, meh, i + 5);
            float cl6 = __shfl_sync(0xFFFFFFFFu, mel, i + 6);
            float ch6 = __shfl_sync(0xFFFFFFFFu, meh, i + 6);
            float cl7 = __shfl_sync(0xFFFFFFFFu, mel, i + 7);
            float ch7 = __shfl_sync(0xFFFFFFFFu, meh, i + 7);

            zl0 = fmaf(a0, cl0, zl0); zl1 = fmaf(b0, cl0, zl1);
            zh0 = fmaf(a0, ch0, zh0); zh1 = fmaf(b0, ch0, zh1);
            zl0 = fmaf(a1, cl1, zl0); zl1 = fmaf(b1, cl1, zl1);
            zh0 = fmaf(a1, ch1, zh0); zh1 = fmaf(b1, ch1, zh1);
            zl0 = fmaf(a2, cl2, zl0); zl1 = fmaf(b2, cl2, zl1);
            zh0 = fmaf(a2, ch2, zh0); zh1 = fmaf(b2, ch2, zh1);
            zl0 = fmaf(a3, cl3, zl0); zl1 = fmaf(b3, cl3, zl1);
            zh0 = fmaf(a3, ch3, zh0); zh1 = fmaf(b3, ch3, zh1);
            zl0 = fmaf(a4, cl4, zl0); zl1 = fmaf(b4, cl4, zl1);
            zh0 = fmaf(a4, ch4, zh0); zh1 = fmaf(b4, ch4, zh1);
            zl0 = fmaf(a5, cl5, zl0); zl1 = fmaf(b5, cl5, zl1);
            zh0 = fmaf(a5, ch5, zh0); zh1 = fmaf(b5, ch5, zh1);
            zl0 = fmaf(a6, cl6, zl0); zl1 = fmaf(b6, cl6, zl1);
            zh0 = fmaf(a6, ch6, zh0); zh1 = fmaf(b6, ch6, zh1);
            zl0 = fmaf(a7, cl7, zl0); zl1 = fmaf(b7, cl7, zl1);
            zh0 = fmaf(a7, ch7, zh0); zh1 = fmaf(b7, ch7, zh1);
        }
        for (; i < cnt; i++) {
            int s0 = __shfl_sync(0xFFFFFFFFu, msrc, i);
            float cl = __shfl_sync(0xFFFFFFFFu, mel, i);
            float ch = __shfl_sync(0xFFFFFFFFu, meh, i);
            const float* p0 = h + (size_t)s0 * D;
            float a0 = p0[lane], b0 = p0[lane + 32];
            zl0 = fmaf(a0, cl, zl0); zl1 = fmaf(b0, cl, zl1);
            zh0 = fmaf(a0, ch, zh0); zh1 = fmaf(b0, ch, zh1);
        }
    }

    float* z = g_z + (size_t)warp * TWO_D;
    z[lane]      = zl0;
    z[lane + 32] = zl1;
    z[lane + 64] = zh0;
    z[lane + 96] = zh1;
}

// ---------------------------------------------------------------------------
// Output projection, register-blocked 4x4 (proven version).
// ---------------------------------------------------------------------------
__global__ void __launch_bounds__(256) out_kernel(const float* __restrict__ br,
                                                  float* __restrict__ out,
                                                  int n)
{
    __shared__ float sW[TWO_D * D];
    __shared__ float sZ[NB * TWO_D];

    int tid = threadIdx.x;
    int node0 = blockIdx.x * NB;

    {
        const float4* Wg = reinterpret_cast<const float4*>(g_WrT);
        float4* Ws = reinterpret_cast<float4*>(sW);
        #pragma unroll
        for (int i = tid; i < (TWO_D * D) / 4; i += 256)
            Ws[i] = Wg[i];
    }
    {
        const float4* Zg = reinterpret_cast<const float4*>(g_z) + (size_t)node0 * (TWO_D / 4);
        float4* Zs = reinterpret_cast<float4*>(sZ);
        #pragma unroll
        for (int i = tid; i < NB * (TWO_D / 4); i += 256) {
            int node = node0 + i / (TWO_D / 4);
            Zs[i] = (node < n) ? Zg[i] : make_float4(0.f, 0.f, 0.f, 0.f);
        }
    }
    __syncthreads();

    int jg = tid & 15;
    int ng = tid >> 4;

    float acc[4][4];
    #pragma unroll
    for (int i = 0; i < 4; i++)
        #pragma unroll
        for (int jj = 0; jj < 4; jj++)
            acc[i][jj] = 0.f;

    const float4* sW4 = reinterpret_cast<const float4*>(sW);
    const float* zbase = sZ + ng * 4 * TWO_D;

    #pragma unroll 4
    for (int k = 0; k < TWO_D; k++) {
        float4 w = sW4[k * (D / 4) + jg];
        float z0 = zbase[0 * TWO_D + k];
        float z1 = zbase[1 * TWO_D + k];
        float z2 = zbase[2 * TWO_D + k];
        float z3 = zbase[3 * TWO_D + k];
        acc[0][0] = fmaf(z0, w.x, acc[0][0]); acc[0][1] = fmaf(z0, w.y, acc[0][1]);
        acc[0][2] = fmaf(z0, w.z, acc[0][2]); acc[0][3] = fmaf(z0, w.w, acc[0][3]);
        acc[1][0] = fmaf(z1, w.x, acc[1][0]); acc[1][1] = fmaf(z1, w.y, acc[1][1]);
        acc[1][2] = fmaf(z1, w.z, acc[1][2]); acc[1][3] = fmaf(z1, w.w, acc[1][3]);
        acc[2][0] = fmaf(z2, w.x, acc[2][0]); acc[2][1] = fmaf(z2, w.y, acc[2][1]);
        acc[2][2] = fmaf(z2, w.z, acc[2][2]); acc[2][3] = fmaf(z2, w.w, acc[2][3]);
        acc[3][0] = fmaf(z3, w.x, acc[3][0]); acc[3][1] = fmaf(z3, w.y, acc[3][1]);
        acc[3][2] = fmaf(z3, w.z, acc[3][2]); acc[3][3] = fmaf(z3, w.w, acc[3][3]);
    }

    int j = jg * 4;
    float4 b4 = *reinterpret_cast<const float4*>(br + j);
    #pragma unroll
    for (int i = 0; i < 4; i++) {
        int node = node0 + ng * 4 + i;
        if (node < n) {
            float4 o;
            o.x = acc[i][0] + b4.x;
            o.y = acc[i][1] + b4.y;
            o.z = acc[i][2] + b4.z;
            o.w = acc[i][3] + b4.w;
            *reinterpret_cast<float4*>(out + (size_t)node * D + j) = o;
        }
    }
}

// ---------------------------------------------------------------------------
extern "C" void kernel_launch(void* const* d_in, const int* in_sizes, int n_in,
                              void* d_out, int out_size)
{
    const float* h   = (const float*)d_in[0];
    const float* dn  = (const float*)d_in[1];
    const int*   src = (const int*)  d_in[2];
    const int*   dst = (const int*)  d_in[3];
    const float* Wl  = (const float*)d_in[4];
    const float* bl  = (const float*)d_in[5];
    const float* Wh  = (const float*)d_in[6];
    const float* bh  = (const float*)d_in[7];
    const float* Wr  = (const float*)d_in[8];
    const float* br  = (const float*)d_in[9];
    float* out = (float*)d_out;

    int n = in_sizes[0] / D;      // nodes
    int e = in_sizes[2];          // edges
    int nb = (n + SCAN_B - 1) / SCAN_B;

    gate_kernel<<<(n * 32 + 255) / 256, 256>>>(h, dn, Wl, Wh, Wr, n);

    hist_kernel<<<((e >> 2) + 255) / 256, 256>>>(dst, e);
    scan1_kernel<<<nb, SCAN_B>>>(n);
    scan3_kernel<<<(n + 255) / 256, 256>>>(n, nb);
    fill_kernel<<<(e + 255) / 256, 256>>>(src, dst, e);

    gather_kernel<<<(int)(((size_t)n * 32 + 255) / 256), 256>>>(h, bl, bh, n);

    out_kernel<<<(n + NB - 1) / NB, 256>>>(br, out, n);
}

// round 13
// speedup vs baseline: 1.0322x; 1.0322x over previous
#include <cuda_runtime.h>
#include <math.h>

#define MAX_N 100000
#define MAX_E 1600000
#define D 64
#define TWO_D 128
#define NB 64
#define SCAN_B 512
#define MAXNB ((MAX_N + SCAN_B - 1) / SCAN_B)   // 196

// Scratch (static __device__ arrays — no allocations allowed)
__device__ float4 g_srcv[MAX_N];                 // (low_src, high_src, dnorm, 0)
__device__ float4 g_dstv[MAX_N];                 // (low_dst, high_dst, dnorm, 0)
__device__ float  g_z[(size_t)MAX_N * TWO_D];    // [N, 2D] aggregation
__device__ float  g_WrT[TWO_D * D];              // Wr transposed [k][j]
__device__ int    g_deg[MAX_N];
__device__ int    g_start[MAX_N];
__device__ int    g_cursor[MAX_N];
__device__ int    g_bsum[MAXNB + 1];
__device__ int    g_esrc[MAX_E];                 // dst-grouped src indices

// ---------------------------------------------------------------------------
// Gate projections: one warp per node. Fused: Wr transpose + deg zero.
// ---------------------------------------------------------------------------
__global__ void gate_kernel(const float* __restrict__ h,
                            const float* __restrict__ dnorm,
                            const float* __restrict__ Wl,
                            const float* __restrict__ Wh,
                            const float* __restrict__ Wr,
                            int n)
{
    int gtid = blockIdx.x * blockDim.x + threadIdx.x;

    if (gtid < D * TWO_D) {
        int j = gtid >> 7;
        int k = gtid & 127;
        g_WrT[k * D + j] = Wr[gtid];
    }
    if (gtid < n) g_deg[gtid] = 0;

    int warp = gtid >> 5;
    int lane = threadIdx.x & 31;
    if (warp >= n) return;

    const float* hp = h + (size_t)warp * D;
    float a0 = hp[lane];
    float a1 = hp[lane + 32];

    float ld = a0 * Wl[lane]      + a1 * Wl[lane + 32];
    float ls = a0 * Wl[lane + 64] + a1 * Wl[lane + 96];
    float hd = a0 * Wh[lane]      + a1 * Wh[lane + 32];
    float hs = a0 * Wh[lane + 64] + a1 * Wh[lane + 96];

    #pragma unroll
    for (int off = 16; off; off >>= 1) {
        ld += __shfl_xor_sync(0xFFFFFFFFu, ld, off);
        ls += __shfl_xor_sync(0xFFFFFFFFu, ls, off);
        hd += __shfl_xor_sync(0xFFFFFFFFu, hd, off);
        hs += __shfl_xor_sync(0xFFFFFFFFu, hs, off);
    }
    if (lane == 0) {
        float dn = dnorm[warp];
        g_srcv[warp] = make_float4(ls, hs, dn, 0.f);
        g_dstv[warp] = make_float4(ld, hd, dn, 0.f);
    }
}

// ---------------------------------------------------------------------------
__global__ void hist_kernel(const int* __restrict__ dst, int e)
{
    int i = blockIdx.x * blockDim.x + threadIdx.x;
    int e4 = e >> 2;
    if (i < e4) {
        int4 d4 = reinterpret_cast<const int4*>(dst)[i];
        atomicAdd(&g_deg[d4.x], 1);
        atomicAdd(&g_deg[d4.y], 1);
        atomicAdd(&g_deg[d4.z], 1);
        atomicAdd(&g_deg[d4.w], 1);
    }
    int t = e4 * 4 + i;
    if (i < (e & 3)) {
        atomicAdd(&g_deg[dst[t]], 1);
    }
}

// ---------------------------------------------------------------------------
__global__ void scan1_kernel(int n)
{
    __shared__ int swarp[16];
    int tid  = threadIdx.x;
    int lane = tid & 31;
    int wid  = tid >> 5;
    int i = blockIdx.x * SCAN_B + tid;
    int v = (i < n) ? g_deg[i] : 0;

    int x = v;
    #pragma unroll
    for (int off = 1; off < 32; off <<= 1) {
        int t = __shfl_up_sync(0xFFFFFFFFu, x, off);
        if (lane >= off) x += t;
    }
    if (lane == 31) swarp[wid] = x;
    __syncthreads();

    if (wid == 0) {
        int w = (lane < 16) ? swarp[lane] : 0;
        #pragma unroll
        for (int off = 1; off < 16; off <<= 1) {
            int t = __shfl_up_sync(0xFFFFFFFFu, w, off);
            if (lane >= off) w += t;
        }
        if (lane < 16) swarp[lane] = w;
    }
    __syncthreads();

    int wbase = (wid > 0) ? swarp[wid - 1] : 0;
    if (i < n) g_start[i] = wbase + x - v;
    if (tid == SCAN_B - 1) g_bsum[blockIdx.x] = wbase + x;
}

// ---------------------------------------------------------------------------
__global__ void scan3_kernel(int n, int nb)
{
    __shared__ int sb[MAXNB];
    __shared__ int swarp[8];
    int tid  = threadIdx.x;
    int lane = tid & 31;
    int wid  = tid >> 5;

    int v = (tid < nb) ? g_bsum[tid] : 0;
    int x = v;
    #pragma unroll
    for (int off = 1; off < 32; off <<= 1) {
        int t = __shfl_up_sync(0xFFFFFFFFu, x, off);
        if (lane >= off) x += t;
    }
    if (lane == 31) swarp[wid] = x;
    __syncthreads();
    if (wid == 0) {
        int w = (lane < 8) ? swarp[lane] : 0;
        #pragma unroll
        for (int off = 1; off < 8; off <<= 1) {
            int t = __shfl_up_sync(0xFFFFFFFFu, w, off);
            if (lane >= off) w += t;
        }
        if (lane < 8) swarp[lane] = w;
    }
    __syncthreads();
    int wbase = (wid > 0) ? swarp[wid - 1] : 0;
    if (tid < nb) sb[tid] = wbase + x - v;
    __syncthreads();

    int i = blockIdx.x * blockDim.x + tid;
    if (i < n) {
        int s = g_start[i] + sb[i / SCAN_B];
        g_start[i] = s;
        g_cursor[i] = s;
    }
}

// ---------------------------------------------------------------------------
// Fill: 2 edges per thread; both atomics issued before both stores so the
// two ATOMG round-trips overlap (1-edge version exposes full 318-cyc chain).
// ---------------------------------------------------------------------------
__global__ void fill_kernel(const int* __restrict__ src,
                            const int* __restrict__ dst,
                            int e)
{
    int i = blockIdx.x * blockDim.x + threadIdx.x;
    int e2 = e >> 1;
    if (i < e2) {
        int2 s2 = reinterpret_cast<const int2*>(src)[i];
        int2 d2 = reinterpret_cast<const int2*>(dst)[i];
        int pos0 = atomicAdd(&g_cursor[d2.x], 1);
        int pos1 = atomicAdd(&g_cursor[d2.y], 1);
        g_esrc[pos0] = s2.x;
        g_esrc[pos1] = s2.y;
    }
    if (i == 0 && (e & 1)) {
        int t = e - 1;
        g_esrc[atomicAdd(&g_cursor[dst[t]], 1)] = src[t];
    }
}

// ---------------------------------------------------------------------------
// Gather-aggregate: one warp per node, strided lanes, unroll 4 (proven).
// ---------------------------------------------------------------------------
__global__ void gather_kernel(const float* __restrict__ h,
                              const float* __restrict__ bl,
                              const float* __restrict__ bh,
                              int n)
{
    int warp = (blockIdx.x * blockDim.x + threadIdx.x) >> 5;
    int lane = threadIdx.x & 31;
    if (warp >= n) return;

    int start = g_start[warp];
    int deg   = g_deg[warp];
    int end   = start + deg;

    float4 dv  = g_dstv[warp];
    float xl_base = dv.x + bl[0];
    float xh_base = dv.y + bh[0];
    float dn_t = dv.z;

    float zl0 = 0.f, zl1 = 0.f, zh0 = 0.f, zh1 = 0.f;

    for (int base = start; base < end; base += 32) {
        int my = base + lane;
        int msrc = 0;
        float mel = 0.f, meh = 0.f;
        if (my < end) {
            msrc = g_esrc[my];
            float4 sv = g_srcv[msrc];
            float xl = xl_base + sv.x;
            float xh = xh_base + sv.y;
            float gl =  tanhf(xl > 0.f ? xl : -0.5f * xl);
            float gh = -tanhf(xh > 0.f ? xh : -0.5f * xh);
            float dd = dn_t * sv.z;
            mel = gl * dd;
            meh = gh * dd;
        }
        int cnt = min(32, end - base);

        int i = 0;
        for (; i + 4 <= cnt; i += 4) {
            int s0 = __shfl_sync(0xFFFFFFFFu, msrc, i);
            int s1 = __shfl_sync(0xFFFFFFFFu, msrc, i + 1);
            int s2 = __shfl_sync(0xFFFFFFFFu, msrc, i + 2);
            int s3 = __shfl_sync(0xFFFFFFFFu, msrc, i + 3);
            float cl0 = __shfl_sync(0xFFFFFFFFu, mel, i);
            float ch0 = __shfl_sync(0xFFFFFFFFu, meh, i);
            float cl1 = __shfl_sync(0xFFFFFFFFu, mel, i + 1);
            float ch1 = __shfl_sync(0xFFFFFFFFu, meh, i + 1);
            float cl2 = __shfl_sync(0xFFFFFFFFu, mel, i + 2);
            float ch2 = __shfl_sync(0xFFFFFFFFu, meh, i + 2);
            float cl3 = __shfl_sync(0xFFFFFFFFu, mel, i + 3);
            float ch3 = __shfl_sync(0xFFFFFFFFu, meh, i + 3);

            const float* p0 = h + (size_t)s0 * D;
            const float* p1 = h + (size_t)s1 * D;
            const float* p2 = h + (size_t)s2 * D;
            const float* p3 = h + (size_t)s3 * D;
            float a0 = p0[lane], b0 = p0[lane + 32];
            float a1 = p1[lane], b1 = p1[lane + 32];
            float a2 = p2[lane], b2 = p2[lane + 32];
            float a3 = p3[lane], b3 = p3[lane + 32];

            zl0 = fmaf(a0, cl0, zl0); zl1 = fmaf(b0, cl0, zl1);
            zh0 = fmaf(a0, ch0, zh0); zh1 = fmaf(b0, ch0, zh1);
            zl0 = fmaf(a1, cl1, zl0); zl1 = fmaf(b1, cl1, zl1);
            zh0 = fmaf(a1, ch1, zh0); zh1 = fmaf(b1, ch1, zh1);
            zl0 = fmaf(a2, cl2, zl0); zl1 = fmaf(b2, cl2, zl1);
            zh0 = fmaf(a2, ch2, zh0); zh1 = fmaf(b2, ch2, zh1);
            zl0 = fmaf(a3, cl3, zl0); zl1 = fmaf(b3, cl3, zl1);
            zh0 = fmaf(a3, ch3, zh0); zh1 = fmaf(b3, ch3, zh1);
        }
        for (; i < cnt; i++) {
            int s0 = __shfl_sync(0xFFFFFFFFu, msrc, i);
            float cl = __shfl_sync(0xFFFFFFFFu, mel, i);
            float ch = __shfl_sync(0xFFFFFFFFu, meh, i);
            const float* p0 = h + (size_t)s0 * D;
            float a0 = p0[lane], b0 = p0[lane + 32];
            zl0 = fmaf(a0, cl, zl0); zl1 = fmaf(b0, cl, zl1);
            zh0 = fmaf(a0, ch, zh0); zh1 = fmaf(b0, ch, zh1);
        }
    }

    float* z = g_z + (size_t)warp * TWO_D;
    z[lane]      = zl0;
    z[lane + 32] = zl1;
    z[lane + 64] = zh0;
    z[lane + 96] = zh1;
}

// ---------------------------------------------------------------------------
// Output projection, register-blocked 4x4 (proven version).
// ---------------------------------------------------------------------------
__global__ void __launch_bounds__(256) out_kernel(const float* __restrict__ br,
                                                  float* __restrict__ out,
                                                  int n)
{
    __shared__ float sW[TWO_D * D];
    __shared__ float sZ[NB * TWO_D];

    int tid = threadIdx.x;
    int node0 = blockIdx.x * NB;

    {
        const float4* Wg = reinterpret_cast<const float4*>(g_WrT);
        float4* Ws = reinterpret_cast<float4*>(sW);
        #pragma unroll
        for (int i = tid; i < (TWO_D * D) / 4; i += 256)
            Ws[i] = Wg[i];
    }
    {
        const float4* Zg = reinterpret_cast<const float4*>(g_z) + (size_t)node0 * (TWO_D / 4);
        float4* Zs = reinterpret_cast<float4*>(sZ);
        #pragma unroll
        for (int i = tid; i < NB * (TWO_D / 4); i += 256) {
            int node = node0 + i / (TWO_D / 4);
            Zs[i] = (node < n) ? Zg[i] : make_float4(0.f, 0.f, 0.f, 0.f);
        }
    }
    __syncthreads();

    int jg = tid & 15;
    int ng = tid >> 4;

    float acc[4][4];
    #pragma unroll
    for (int i = 0; i < 4; i++)
        #pragma unroll
        for (int jj = 0; jj < 4; jj++)
            acc[i][jj] = 0.f;

    const float4* sW4 = reinterpret_cast<const float4*>(sW);
    const float* zbase = sZ + ng * 4 * TWO_D;

    #pragma unroll 4
    for (int k = 0; k < TWO_D; k++) {
        float4 w = sW4[k * (D / 4) + jg];
        float z0 = zbase[0 * TWO_D + k];
        float z1 = zbase[1 * TWO_D + k];
        float z2 = zbase[2 * TWO_D + k];
        float z3 = zbase[3 * TWO_D + k];
        acc[0][0] = fmaf(z0, w.x, acc[0][0]); acc[0][1] = fmaf(z0, w.y, acc[0][1]);
        acc[0][2] = fmaf(z0, w.z, acc[0][2]); acc[0][3] = fmaf(z0, w.w, acc[0][3]);
        acc[1][0] = fmaf(z1, w.x, acc[1][0]); acc[1][1] = fmaf(z1, w.y, acc[1][1]);
        acc[1][2] = fmaf(z1, w.z, acc[1][2]); acc[1][3] = fmaf(z1, w.w, acc[1][3]);
        acc[2][0] = fmaf(z2, w.x, acc[2][0]); acc[2][1] = fmaf(z2, w.y, acc[2][1]);
        acc[2][2] = fmaf(z2, w.z, acc[2][2]); acc[2][3] = fmaf(z2, w.w, acc[2][3]);
        acc[3][0] = fmaf(z3, w.x, acc[3][0]); acc[3][1] = fmaf(z3, w.y, acc[3][1]);
        acc[3][2] = fmaf(z3, w.z, acc[3][2]); acc[3][3] = fmaf(z3, w.w, acc[3][3]);
    }

    int j = jg * 4;
    float4 b4 = *reinterpret_cast<const float4*>(br + j);
    #pragma unroll
    for (int i = 0; i < 4; i++) {
        int node = node0 + ng * 4 + i;
        if (node < n) {
            float4 o;
            o.x = acc[i][0] + b4.x;
            o.y = acc[i][1] + b4.y;
            o.z = acc[i][2] + b4.z;
            o.w = acc[i][3] + b4.w;
            *reinterpret_cast<float4*>(out + (size_t)node * D + j) = o;
        }
    }
}

// ---------------------------------------------------------------------------
extern "C" void kernel_launch(void* const* d_in, const int* in_sizes, int n_in,
                              void* d_out, int out_size)
{
    const float* h   = (const float*)d_in[0];
    const float* dn  = (const float*)d_in[1];
    const int*   src = (const int*)  d_in[2];
    const int*   dst = (const int*)  d_in[3];
    const float* Wl  = (const float*)d_in[4];
    const float* bl  = (const float*)d_in[5];
    const float* Wh  = (const float*)d_in[6];
    const float* bh  = (const float*)d_in[7];
    const float* Wr  = (const float*)d_in[8];
    const float* br  = (const float*)d_in[9];
    float* out = (float*)d_out;

    int n = in_sizes[0] / D;      // nodes
    int e = in_sizes[2];          // edges
    int nb = (n + SCAN_B - 1) / SCAN_B;

    gate_kernel<<<(n * 32 + 255) / 256, 256>>>(h, dn, Wl, Wh, Wr, n);

    hist_kernel<<<((e >> 2) + 255) / 256, 256>>>(dst, e);
    scan1_kernel<<<nb, SCAN_B>>>(n);
    scan3_kernel<<<(n + 255) / 256, 256>>>(n, nb);
    fill_kernel<<<((e >> 1) + 255) / 256, 256>>>(src, dst, e);

    gather_kernel<<<(int)(((size_t)n * 32 + 255) / 256), 256>>>(h, bl, bh, n);

    out_kernel<<<(n + NB - 1) / NB, 256>>>(br, out, n);
}

// round 15
// speedup vs baseline: 1.1571x; 1.1210x over previous
#include <cuda_runtime.h>
#include <cuda_bf16.h>
#include <math.h>
#include <stdint.h>

#define MAX_N 100000
#define MAX_E 1600000
#define D 64
#define TWO_D 128
#define SCAN_B 512
#define MAXNB ((MAX_N + SCAN_B - 1) / SCAN_B)   // 196

// Scratch (static __device__ arrays — no allocations allowed)
__device__ float4 g_srcv[MAX_N];                 // (low_src, high_src, dnorm, 0)
__device__ float4 g_dstv[MAX_N];                 // (low_dst, high_dst, dnorm, 0)
__device__ float  g_z[(size_t)MAX_N * TWO_D];    // [N, 2D] aggregation
__device__ int    g_deg[MAX_N];
__device__ int    g_start[MAX_N];
__device__ int    g_cursor[MAX_N];
__device__ int    g_bsum[MAXNB + 1];
__device__ int    g_esrc[MAX_E];                 // dst-grouped src indices

// ---------------------------------------------------------------------------
// bf16 split helpers + mma.sync (baseline PTX — no sm_103a features)
// ---------------------------------------------------------------------------
__device__ __forceinline__ void split2(float x, float y, uint32_t& hi, uint32_t& lo)
{
    __nv_bfloat16 hx = __float2bfloat16(x);
    __nv_bfloat16 hy = __float2bfloat16(y);
    float rx = x - __bfloat162float(hx);
    float ry = y - __bfloat162float(hy);
    __nv_bfloat162 H; H.x = hx; H.y = hy;
    __nv_bfloat162 L = __floats2bfloat162_rn(rx, ry);
    hi = *reinterpret_cast<uint32_t*>(&H);
    lo = *reinterpret_cast<uint32_t*>(&L);
}

#define MMA_BF16(d, a0, a1, a2, a3, b0, b1) \
    asm volatile("mma.sync.aligned.m16n8k16.row.col.f32.bf16.bf16.f32 " \
        "{%0,%1,%2,%3}, {%4,%5,%6,%7}, {%8,%9}, {%0,%1,%2,%3};" \
        : "+f"((d)[0]), "+f"((d)[1]), "+f"((d)[2]), "+f"((d)[3]) \
        : "r"(a0), "r"(a1), "r"(a2), "r"(a3), "r"(b0), "r"(b1))

// ---------------------------------------------------------------------------
// Gate projections: one warp per node. Fused: deg zero.
// ---------------------------------------------------------------------------
__global__ void gate_kernel(const float* __restrict__ h,
                            const float* __restrict__ dnorm,
                            const float* __restrict__ Wl,
                            const float* __restrict__ Wh,
                            int n)
{
    int gtid = blockIdx.x * blockDim.x + threadIdx.x;
    if (gtid < n) g_deg[gtid] = 0;

    int warp = gtid >> 5;
    int lane = threadIdx.x & 31;
    if (warp >= n) return;

    const float* hp = h + (size_t)warp * D;
    float a0 = hp[lane];
    float a1 = hp[lane + 32];

    float ld = a0 * Wl[lane]      + a1 * Wl[lane + 32];
    float ls = a0 * Wl[lane + 64] + a1 * Wl[lane + 96];
    float hd = a0 * Wh[lane]      + a1 * Wh[lane + 32];
    float hs = a0 * Wh[lane + 64] + a1 * Wh[lane + 96];

    #pragma unroll
    for (int off = 16; off; off >>= 1) {
        ld += __shfl_xor_sync(0xFFFFFFFFu, ld, off);
        ls += __shfl_xor_sync(0xFFFFFFFFu, ls, off);
        hd += __shfl_xor_sync(0xFFFFFFFFu, hd, off);
        hs += __shfl_xor_sync(0xFFFFFFFFu, hs, off);
    }
    if (lane == 0) {
        float dn = dnorm[warp];
        g_srcv[warp] = make_float4(ls, hs, dn, 0.f);
        g_dstv[warp] = make_float4(ld, hd, dn, 0.f);
    }
}

// ---------------------------------------------------------------------------
__global__ void hist_kernel(const int* __restrict__ dst, int e)
{
    int i = blockIdx.x * blockDim.x + threadIdx.x;
    int e4 = e >> 2;
    if (i < e4) {
        int4 d4 = reinterpret_cast<const int4*>(dst)[i];
        atomicAdd(&g_deg[d4.x], 1);
        atomicAdd(&g_deg[d4.y], 1);
        atomicAdd(&g_deg[d4.z], 1);
        atomicAdd(&g_deg[d4.w], 1);
    }
    int t = e4 * 4 + i;
    if (i < (e & 3)) atomicAdd(&g_deg[dst[t]], 1);
}

// ---------------------------------------------------------------------------
__global__ void scan1_kernel(int n)
{
    __shared__ int swarp[16];
    int tid  = threadIdx.x;
    int lane = tid & 31;
    int wid  = tid >> 5;
    int i = blockIdx.x * SCAN_B + tid;
    int v = (i < n) ? g_deg[i] : 0;

    int x = v;
    #pragma unroll
    for (int off = 1; off < 32; off <<= 1) {
        int t = __shfl_up_sync(0xFFFFFFFFu, x, off);
        if (lane >= off) x += t;
    }
    if (lane == 31) swarp[wid] = x;
    __syncthreads();
    if (wid == 0) {
        int w = (lane < 16) ? swarp[lane] : 0;
        #pragma unroll
        for (int off = 1; off < 16; off <<= 1) {
            int t = __shfl_up_sync(0xFFFFFFFFu, w, off);
            if (lane >= off) w += t;
        }
        if (lane < 16) swarp[lane] = w;
    }
    __syncthreads();
    int wbase = (wid > 0) ? swarp[wid - 1] : 0;
    if (i < n) g_start[i] = wbase + x - v;
    if (tid == SCAN_B - 1) g_bsum[blockIdx.x] = wbase + x;
}

// ---------------------------------------------------------------------------
__global__ void scan3_kernel(int n, int nb)
{
    __shared__ int sb[MAXNB];
    __shared__ int swarp[8];
    int tid  = threadIdx.x;
    int lane = tid & 31;
    int wid  = tid >> 5;

    int v = (tid < nb) ? g_bsum[tid] : 0;
    int x = v;
    #pragma unroll
    for (int off = 1; off < 32; off <<= 1) {
        int t = __shfl_up_sync(0xFFFFFFFFu, x, off);
        if (lane >= off) x += t;
    }
    if (lane == 31) swarp[wid] = x;
    __syncthreads();
    if (wid == 0) {
        int w = (lane < 8) ? swarp[lane] : 0;
        #pragma unroll
        for (int off = 1; off < 8; off <<= 1) {
            int t = __shfl_up_sync(0xFFFFFFFFu, w, off);
            if (lane >= off) w += t;
        }
        if (lane < 8) swarp[lane] = w;
    }
    __syncthreads();
    int wbase = (wid > 0) ? swarp[wid - 1] : 0;
    if (tid < nb) sb[tid] = wbase + x - v;
    __syncthreads();

    int i = blockIdx.x * blockDim.x + tid;
    if (i < n) {
        int s = g_start[i] + sb[i / SCAN_B];
        g_start[i] = s;
        g_cursor[i] = s;
    }
}

// ---------------------------------------------------------------------------
__global__ void fill_kernel(const int* __restrict__ src,
                            const int* __restrict__ dst,
                            int e)
{
    int i = blockIdx.x * blockDim.x + threadIdx.x;
    if (i >= e) return;
    int pos = atomicAdd(&g_cursor[dst[i]], 1);
    g_esrc[pos] = src[i];
}

// ---------------------------------------------------------------------------
// Gather-aggregate: one warp per node, strided lanes, unroll 4 (proven).
// ---------------------------------------------------------------------------
__global__ void gather_kernel(const float* __restrict__ h,
                              const float* __restrict__ bl,
                              const float* __restrict__ bh,
                              int n)
{
    int warp = (blockIdx.x * blockDim.x + threadIdx.x) >> 5;
    int lane = threadIdx.x & 31;
    if (warp >= n) return;

    int start = g_start[warp];
    int deg   = g_deg[warp];
    int end   = start + deg;

    float4 dv  = g_dstv[warp];
    float xl_base = dv.x + bl[0];
    float xh_base = dv.y + bh[0];
    float dn_t = dv.z;

    float zl0 = 0.f, zl1 = 0.f, zh0 = 0.f, zh1 = 0.f;

    for (int base = start; base < end; base += 32) {
        int my = base + lane;
        int msrc = 0;
        float mel = 0.f, meh = 0.f;
        if (my < end) {
            msrc = g_esrc[my];
            float4 sv = g_srcv[msrc];
            float xl = xl_base + sv.x;
            float xh = xh_base + sv.y;
            float gl =  tanhf(xl > 0.f ? xl : -0.5f * xl);
            float gh = -tanhf(xh > 0.f ? xh : -0.5f * xh);
            float dd = dn_t * sv.z;
            mel = gl * dd;
            meh = gh * dd;
        }
        int cnt = min(32, end - base);

        int i = 0;
        for (; i + 4 <= cnt; i += 4) {
            int s0 = __shfl_sync(0xFFFFFFFFu, msrc, i);
            int s1 = __shfl_sync(0xFFFFFFFFu, msrc, i + 1);
            int s2 = __shfl_sync(0xFFFFFFFFu, msrc, i + 2);
            int s3 = __shfl_sync(0xFFFFFFFFu, msrc, i + 3);
            float cl0 = __shfl_sync(0xFFFFFFFFu, mel, i);
            float ch0 = __shfl_sync(0xFFFFFFFFu, meh, i);
            float cl1 = __shfl_sync(0xFFFFFFFFu, mel, i + 1);
            float ch1 = __shfl_sync(0xFFFFFFFFu, meh, i + 1);
            float cl2 = __shfl_sync(0xFFFFFFFFu, mel, i + 2);
            float ch2 = __shfl_sync(0xFFFFFFFFu, meh, i + 2);
            float cl3 = __shfl_sync(0xFFFFFFFFu, mel, i + 3);
            float ch3 = __shfl_sync(0xFFFFFFFFu, meh, i + 3);

            const float* p0 = h + (size_t)s0 * D;
            const float* p1 = h + (size_t)s1 * D;
            const float* p2 = h + (size_t)s2 * D;
            const float* p3 = h + (size_t)s3 * D;
            float a0 = p0[lane], b0 = p0[lane + 32];
            float a1 = p1[lane], b1 = p1[lane + 32];
            float a2 = p2[lane], b2 = p2[lane + 32];
            float a3 = p3[lane], b3 = p3[lane + 32];

            zl0 = fmaf(a0, cl0, zl0); zl1 = fmaf(b0, cl0, zl1);
            zh0 = fmaf(a0, ch0, zh0); zh1 = fmaf(b0, ch0, zh1);
            zl0 = fmaf(a1, cl1, zl0); zl1 = fmaf(b1, cl1, zl1);
            zh0 = fmaf(a1, ch1, zh0); zh1 = fmaf(b1, ch1, zh1);
            zl0 = fmaf(a2, cl2, zl0); zl1 = fmaf(b2, cl2, zl1);
            zh0 = fmaf(a2, ch2, zh0); zh1 = fmaf(b2, ch2, zh1);
            zl0 = fmaf(a3, cl3, zl0); zl1 = fmaf(b3, cl3, zl1);
            zh0 = fmaf(a3, ch3, zh0); zh1 = fmaf(b3, ch3, zh1);
        }
        for (; i < cnt; i++) {
            int s0 = __shfl_sync(0xFFFFFFFFu, msrc, i);
            float cl = __shfl_sync(0xFFFFFFFFu, mel, i);
            float ch = __shfl_sync(0xFFFFFFFFu, meh, i);
            const float* p0 = h + (size_t)s0 * D;
            float a0 = p0[lane], b0 = p0[lane + 32];
            zl0 = fmaf(a0, cl, zl0); zl1 = fmaf(b0, cl, zl1);
            zh0 = fmaf(a0, ch, zh0); zh1 = fmaf(b0, ch, zh1);
        }
    }

    float* z = g_z + (size_t)warp * TWO_D;
    z[lane]      = zl0;
    z[lane + 32] = zl1;
    z[lane + 64] = zh0;
    z[lane + 96] = zh1;
}

// ---------------------------------------------------------------------------
// Output projection via mma.sync bf16 split-GEMM (HMMA — baseline PTX).
// Per CTA: 128 nodes, 8 warps, each warp one 16-row m-tile x full N=64.
// B (Wr) fragments staged once in smem in fragment order (conflict-free LDS.64).
// A fragments loaded straight from g_z and split hi/lo in registers.
// D = Ah*Bh + Ah*Bl + Al*Bh (fp32 accum).
// ---------------------------------------------------------------------------
__global__ void __launch_bounds__(256) out_mma_kernel(
    const float* __restrict__ Wr,
    const float* __restrict__ br,
    float* __restrict__ out,
    int n)
{
    // B fragments: [nt][kt][lane] -> uint2 {b0, b1}. 8*8*32 = 2048 entries.
    __shared__ uint2 sBhi[2048];
    __shared__ uint2 sBlo[2048];

    int tid  = threadIdx.x;
    int lane = tid & 31;
    int w    = tid >> 5;
    int tg   = lane & 3;
    int g    = lane >> 2;

    // Stage B fragments (Wr is 64x128 row-major; col-major B == Wr[j,k])
    for (int e = tid; e < 2048; e += 256) {
        int ln = e & 31;
        int kt = (e >> 5) & 7;
        int nt = e >> 8;
        int etg = ln & 3;
        int eg  = ln >> 2;
        int nrow = nt * 8 + eg;
        int k0 = kt * 16 + 2 * etg;
        float2 v0 = *reinterpret_cast<const float2*>(Wr + nrow * TWO_D + k0);
        float2 v1 = *reinterpret_cast<const float2*>(Wr + nrow * TWO_D + k0 + 8);
        uint32_t h0, l0, h1, l1;
        split2(v0.x, v0.y, h0, l0);
        split2(v1.x, v1.y, h1, l1);
        sBhi[e] = make_uint2(h0, h1);
        sBlo[e] = make_uint2(l0, l1);
    }
    __syncthreads();

    int m0 = blockIdx.x * 128 + w * 16;
    int r0 = m0 + g;
    int r1 = m0 + g + 8;
    bool p0 = r0 < n;
    bool p1 = r1 < n;

    float acc[8][4];
    #pragma unroll
    for (int nt = 0; nt < 8; nt++)
        #pragma unroll
        for (int q = 0; q < 4; q++)
            acc[nt][q] = 0.f;

    const float2* z2 = reinterpret_cast<const float2*>(g_z);
    const float2 zero2 = make_float2(0.f, 0.f);

    #pragma unroll
    for (int kt = 0; kt < 8; kt++) {
        int k0 = kt * 16 + 2 * tg;
        float2 v00 = p0 ? z2[(size_t)r0 * 64 + (k0 >> 1)]     : zero2;
        float2 v01 = p0 ? z2[(size_t)r0 * 64 + (k0 >> 1) + 4] : zero2;
        float2 v10 = p1 ? z2[(size_t)r1 * 64 + (k0 >> 1)]     : zero2;
        float2 v11 = p1 ? z2[(size_t)r1 * 64 + (k0 >> 1) + 4] : zero2;

        uint32_t a0h, a0l, a1h, a1l, a2h, a2l, a3h, a3l;
        split2(v00.x, v00.y, a0h, a0l);   // (g,   k0..k0+1)
        split2(v10.x, v10.y, a1h, a1l);   // (g+8, k0..k0+1)
        split2(v01.x, v01.y, a2h, a2l);   // (g,   k0+8..k0+9)
        split2(v11.x, v11.y, a3h, a3l);   // (g+8, k0+8..k0+9)

        #pragma unroll
        for (int nt = 0; nt < 8; nt++) {
            uint2 bh = sBhi[nt * 256 + kt * 32 + lane];
            uint2 bl = sBlo[nt * 256 + kt * 32 + lane];
            MMA_BF16(acc[nt], a0h, a1h, a2h, a3h, bh.x, bh.y);
            MMA_BF16(acc[nt], a0h, a1h, a2h, a3h, bl.x, bl.y);
            MMA_BF16(acc[nt], a0l, a1l, a2l, a3l, bh.x, bh.y);
        }
    }

    // Epilogue: d0->(g,c0), d1->(g,c0+1), d2->(g+8,c0), d3->(g+8,c0+1)
    #pragma unroll
    for (int nt = 0; nt < 8; nt++) {
        int c0 = nt * 8 + 2 * tg;
        float2 b2 = *reinterpret_cast<const float2*>(br + c0);
        if (p0) {
            float2 o = make_float2(acc[nt][0] + b2.x, acc[nt][1] + b2.y);
            *reinterpret_cast<float2*>(out + (size_t)r0 * D + c0) = o;
        }
        if (p1) {
            float2 o = make_float2(acc[nt][2] + b2.x, acc[nt][3] + b2.y);
            *reinterpret_cast<float2*>(out + (size_t)r1 * D + c0) = o;
        }
    }
}

// ---------------------------------------------------------------------------
extern "C" void kernel_launch(void* const* d_in, const int* in_sizes, int n_in,
                              void* d_out, int out_size)
{
    const float* h   = (const float*)d_in[0];
    const float* dn  = (const float*)d_in[1];
    const int*   src = (const int*)  d_in[2];
    const int*   dst = (const int*)  d_in[3];
    const float* Wl  = (const float*)d_in[4];
    const float* bl  = (const float*)d_in[5];
    const float* Wh  = (const float*)d_in[6];
    const float* bh  = (const float*)d_in[7];
    const float* Wr  = (const float*)d_in[8];
    const float* br  = (const float*)d_in[9];
    float* out = (float*)d_out;

    int n = in_sizes[0] / D;      // nodes
    int e = in_sizes[2];          // edges
    int nb = (n + SCAN_B - 1) / SCAN_B;

    gate_kernel<<<(n * 32 + 255) / 256, 256>>>(h, dn, Wl, Wh, n);

    hist_kernel<<<((e >> 2) + 255) / 256, 256>>>(dst, e);
    scan1_kernel<<<nb, SCAN_B>>>(n);
    scan3_kernel<<<(n + 255) / 256, 256>>>(n, nb);
    fill_kernel<<<(e + 255) / 256, 256>>>(src, dst, e);

    gather_kernel<<<(int)(((size_t)n * 32 + 255) / 256), 256>>>(h, bl, bh, n);

    out_mma_kernel<<<(n + 127) / 128, 256>>>(Wr, br, out, n);
}

// round 16
// speedup vs baseline: 1.1917x; 1.0299x over previous
#include <cuda_runtime.h>
#include <cuda_bf16.h>
#include <math.h>
#include <stdint.h>

#define MAX_N 100000
#define MAX_E 1600000
#define D 64
#define TWO_D 128
#define SCAN_B 512
#define MAXNB ((MAX_N + SCAN_B - 1) / SCAN_B)   // 196

// Scratch (static __device__ arrays — no allocations allowed)
__device__ float4 g_srcv[MAX_N];                 // (low_src, high_src, dnorm, 0)
__device__ float4 g_dstv[MAX_N];                 // (low_dst, high_dst, dnorm, 0)
__device__ float  g_z[(size_t)MAX_N * TWO_D];    // [N, 2D] aggregation
__device__ int    g_deg[MAX_N];
__device__ int    g_start[MAX_N];
__device__ int    g_cursor[MAX_N];
__device__ int    g_bsum[MAXNB + 1];
__device__ int    g_esrc[MAX_E];                 // dst-grouped src indices

// ---------------------------------------------------------------------------
// bf16 split helpers + mma.sync (baseline PTX — no sm_103a features)
// ---------------------------------------------------------------------------
__device__ __forceinline__ void split2(float x, float y, uint32_t& hi, uint32_t& lo)
{
    __nv_bfloat16 hx = __float2bfloat16(x);
    __nv_bfloat16 hy = __float2bfloat16(y);
    float rx = x - __bfloat162float(hx);
    float ry = y - __bfloat162float(hy);
    __nv_bfloat162 H; H.x = hx; H.y = hy;
    __nv_bfloat162 L = __floats2bfloat162_rn(rx, ry);
    hi = *reinterpret_cast<uint32_t*>(&H);
    lo = *reinterpret_cast<uint32_t*>(&L);
}

#define MMA_BF16(d, a0, a1, a2, a3, b0, b1) \
    asm volatile("mma.sync.aligned.m16n8k16.row.col.f32.bf16.bf16.f32 " \
        "{%0,%1,%2,%3}, {%4,%5,%6,%7}, {%8,%9}, {%0,%1,%2,%3};" \
        : "+f"((d)[0]), "+f"((d)[1]), "+f"((d)[2]), "+f"((d)[3]) \
        : "r"(a0), "r"(a1), "r"(a2), "r"(a3), "r"(b0), "r"(b1))

// ---------------------------------------------------------------------------
// Gate projections: one warp per node. Fused: deg zero.
// ---------------------------------------------------------------------------
__global__ void gate_kernel(const float* __restrict__ h,
                            const float* __restrict__ dnorm,
                            const float* __restrict__ Wl,
                            const float* __restrict__ Wh,
                            int n)
{
    int gtid = blockIdx.x * blockDim.x + threadIdx.x;
    if (gtid < n) g_deg[gtid] = 0;

    int warp = gtid >> 5;
    int lane = threadIdx.x & 31;
    if (warp >= n) return;

    const float* hp = h + (size_t)warp * D;
    float a0 = hp[lane];
    float a1 = hp[lane + 32];

    float ld = a0 * Wl[lane]      + a1 * Wl[lane + 32];
    float ls = a0 * Wl[lane + 64] + a1 * Wl[lane + 96];
    float hd = a0 * Wh[lane]      + a1 * Wh[lane + 32];
    float hs = a0 * Wh[lane + 64] + a1 * Wh[lane + 96];

    #pragma unroll
    for (int off = 16; off; off >>= 1) {
        ld += __shfl_xor_sync(0xFFFFFFFFu, ld, off);
        ls += __shfl_xor_sync(0xFFFFFFFFu, ls, off);
        hd += __shfl_xor_sync(0xFFFFFFFFu, hd, off);
        hs += __shfl_xor_sync(0xFFFFFFFFu, hs, off);
    }
    if (lane == 0) {
        float dn = dnorm[warp];
        g_srcv[warp] = make_float4(ls, hs, dn, 0.f);
        g_dstv[warp] = make_float4(ld, hd, dn, 0.f);
    }
}

// ---------------------------------------------------------------------------
__global__ void hist_kernel(const int* __restrict__ dst, int e)
{
    int i = blockIdx.x * blockDim.x + threadIdx.x;
    int e4 = e >> 2;
    if (i < e4) {
        int4 d4 = reinterpret_cast<const int4*>(dst)[i];
        atomicAdd(&g_deg[d4.x], 1);
        atomicAdd(&g_deg[d4.y], 1);
        atomicAdd(&g_deg[d4.z], 1);
        atomicAdd(&g_deg[d4.w], 1);
    }
    int t = e4 * 4 + i;
    if (i < (e & 3)) atomicAdd(&g_deg[dst[t]], 1);
}

// ---------------------------------------------------------------------------
__global__ void scan1_kernel(int n)
{
    __shared__ int swarp[16];
    int tid  = threadIdx.x;
    int lane = tid & 31;
    int wid  = tid >> 5;
    int i = blockIdx.x * SCAN_B + tid;
    int v = (i < n) ? g_deg[i] : 0;

    int x = v;
    #pragma unroll
    for (int off = 1; off < 32; off <<= 1) {
        int t = __shfl_up_sync(0xFFFFFFFFu, x, off);
        if (lane >= off) x += t;
    }
    if (lane == 31) swarp[wid] = x;
    __syncthreads();
    if (wid == 0) {
        int w = (lane < 16) ? swarp[lane] : 0;
        #pragma unroll
        for (int off = 1; off < 16; off <<= 1) {
            int t = __shfl_up_sync(0xFFFFFFFFu, w, off);
            if (lane >= off) w += t;
        }
        if (lane < 16) swarp[lane] = w;
    }
    __syncthreads();
    int wbase = (wid > 0) ? swarp[wid - 1] : 0;
    if (i < n) g_start[i] = wbase + x - v;
    if (tid == SCAN_B - 1) g_bsum[blockIdx.x] = wbase + x;
}

// ---------------------------------------------------------------------------
__global__ void scan3_kernel(int n, int nb)
{
    __shared__ int sb[MAXNB];
    __shared__ int swarp[8];
    int tid  = threadIdx.x;
    int lane = tid & 31;
    int wid  = tid >> 5;

    int v = (tid < nb) ? g_bsum[tid] : 0;
    int x = v;
    #pragma unroll
    for (int off = 1; off < 32; off <<= 1) {
        int t = __shfl_up_sync(0xFFFFFFFFu, x, off);
        if (lane >= off) x += t;
    }
    if (lane == 31) swarp[wid] = x;
    __syncthreads();
    if (wid == 0) {
        int w = (lane < 8) ? swarp[lane] : 0;
        #pragma unroll
        for (int off = 1; off < 8; off <<= 1) {
            int t = __shfl_up_sync(0xFFFFFFFFu, w, off);
            if (lane >= off) w += t;
        }
        if (lane < 8) swarp[lane] = w;
    }
    __syncthreads();
    int wbase = (wid > 0) ? swarp[wid - 1] : 0;
    if (tid < nb) sb[tid] = wbase + x - v;
    __syncthreads();

    int i = blockIdx.x * blockDim.x + tid;
    if (i < n) {
        int s = g_start[i] + sb[i / SCAN_B];
        g_start[i] = s;
        g_cursor[i] = s;
    }
}

// ---------------------------------------------------------------------------
__global__ void fill_kernel(const int* __restrict__ src,
                            const int* __restrict__ dst,
                            int e)
{
    int i = blockIdx.x * blockDim.x + threadIdx.x;
    if (i >= e) return;
    int pos = atomicAdd(&g_cursor[dst[i]], 1);
    g_esrc[pos] = src[i];
}

// ---------------------------------------------------------------------------
// Gather-aggregate v3: TWO nodes per warp (one per half-warp).
// Lane hl owns k-quad [4hl, 4hl+4): one LDG.128 per edge per half —
// a single warp-wide load instruction covers 2 edge rows.
// 16-edge chunks match avg degree; coef lanes fully utilized.
// ---------------------------------------------------------------------------
__global__ void gather_kernel(const float* __restrict__ h,
                              const float* __restrict__ bl,
                              const float* __restrict__ bh,
                              int n)
{
    int warp = (blockIdx.x * blockDim.x + threadIdx.x) >> 5;
    int lane = threadIdx.x & 31;
    int half = lane >> 4;
    int hl   = lane & 15;
    unsigned hmask = 0xFFFFu << (half * 16);
    int hbase = half << 4;

    int node = warp * 2 + half;
    bool valid = node < n;

    int start = 0, end = 0;
    float xl_base = 0.f, xh_base = 0.f, dn_t = 0.f;
    if (valid) {
        start = g_start[node];
        end   = start + g_deg[node];
        float4 dv = g_dstv[node];
        xl_base = dv.x + bl[0];
        xh_base = dv.y + bh[0];
        dn_t    = dv.z;
    }

    float4 zl = make_float4(0.f, 0.f, 0.f, 0.f);
    float4 zh = make_float4(0.f, 0.f, 0.f, 0.f);

    for (int base = start; base < end; base += 16) {
        int my = base + hl;
        int msrc = 0;
        float mel = 0.f, meh = 0.f;
        if (my < end) {
            msrc = g_esrc[my];
            float4 sv = g_srcv[msrc];
            float xl = xl_base + sv.x;
            float xh = xh_base + sv.y;
            float gl =  tanhf(xl > 0.f ? xl : -0.5f * xl);
            float gh = -tanhf(xh > 0.f ? xh : -0.5f * xh);
            float dd = dn_t * sv.z;
            mel = gl * dd;
            meh = gh * dd;
        }
        int cnt = min(16, end - base);

        int i = 0;
        for (; i + 4 <= cnt; i += 4) {
            int s0 = __shfl_sync(hmask, msrc, hbase + i);
            int s1 = __shfl_sync(hmask, msrc, hbase + i + 1);
            int s2 = __shfl_sync(hmask, msrc, hbase + i + 2);
            int s3 = __shfl_sync(hmask, msrc, hbase + i + 3);
            float cl0 = __shfl_sync(hmask, mel, hbase + i);
            float ch0 = __shfl_sync(hmask, meh, hbase + i);
            float cl1 = __shfl_sync(hmask, mel, hbase + i + 1);
            float ch1 = __shfl_sync(hmask, meh, hbase + i + 1);
            float cl2 = __shfl_sync(hmask, mel, hbase + i + 2);
            float ch2 = __shfl_sync(hmask, meh, hbase + i + 2);
            float cl3 = __shfl_sync(hmask, mel, hbase + i + 3);
            float ch3 = __shfl_sync(hmask, meh, hbase + i + 3);

            float4 v0 = reinterpret_cast<const float4*>(h + (size_t)s0 * D)[hl];
            float4 v1 = reinterpret_cast<const float4*>(h + (size_t)s1 * D)[hl];
            float4 v2 = reinterpret_cast<const float4*>(h + (size_t)s2 * D)[hl];
            float4 v3 = reinterpret_cast<const float4*>(h + (size_t)s3 * D)[hl];

            zl.x = fmaf(v0.x, cl0, zl.x); zl.y = fmaf(v0.y, cl0, zl.y);
            zl.z = fmaf(v0.z, cl0, zl.z); zl.w = fmaf(v0.w, cl0, zl.w);
            zh.x = fmaf(v0.x, ch0, zh.x); zh.y = fmaf(v0.y, ch0, zh.y);
            zh.z = fmaf(v0.z, ch0, zh.z); zh.w = fmaf(v0.w, ch0, zh.w);

            zl.x = fmaf(v1.x, cl1, zl.x); zl.y = fmaf(v1.y, cl1, zl.y);
            zl.z = fmaf(v1.z, cl1, zl.z); zl.w = fmaf(v1.w, cl1, zl.w);
            zh.x = fmaf(v1.x, ch1, zh.x); zh.y = fmaf(v1.y, ch1, zh.y);
            zh.z = fmaf(v1.z, ch1, zh.z); zh.w = fmaf(v1.w, ch1, zh.w);

            zl.x = fmaf(v2.x, cl2, zl.x); zl.y = fmaf(v2.y, cl2, zl.y);
            zl.z = fmaf(v2.z, cl2, zl.z); zl.w = fmaf(v2.w, cl2, zl.w);
            zh.x = fmaf(v2.x, ch2, zh.x); zh.y = fmaf(v2.y, ch2, zh.y);
            zh.z = fmaf(v2.z, ch2, zh.z); zh.w = fmaf(v2.w, ch2, zh.w);

            zl.x = fmaf(v3.x, cl3, zl.x); zl.y = fmaf(v3.y, cl3, zl.y);
            zl.z = fmaf(v3.z, cl3, zl.z); zl.w = fmaf(v3.w, cl3, zl.w);
            zh.x = fmaf(v3.x, ch3, zh.x); zh.y = fmaf(v3.y, ch3, zh.y);
            zh.z = fmaf(v3.z, ch3, zh.z); zh.w = fmaf(v3.w, ch3, zh.w);
        }
        for (; i < cnt; i++) {
            int s0   = __shfl_sync(hmask, msrc, hbase + i);
            float cl = __shfl_sync(hmask, mel,  hbase + i);
            float ch = __shfl_sync(hmask, meh,  hbase + i);
            float4 v0 = reinterpret_cast<const float4*>(h + (size_t)s0 * D)[hl];
            zl.x = fmaf(v0.x, cl, zl.x); zl.y = fmaf(v0.y, cl, zl.y);
            zl.z = fmaf(v0.z, cl, zl.z); zl.w = fmaf(v0.w, cl, zl.w);
            zh.x = fmaf(v0.x, ch, zh.x); zh.y = fmaf(v0.y, ch, zh.y);
            zh.z = fmaf(v0.z, ch, zh.z); zh.w = fmaf(v0.w, ch, zh.w);
        }
    }

    if (valid) {
        float* z = g_z + (size_t)node * TWO_D;
        reinterpret_cast<float4*>(z)[hl]      = zl;   // z_low quad
        reinterpret_cast<float4*>(z + D)[hl]  = zh;   // z_high quad
    }
}

// ---------------------------------------------------------------------------
// Output projection via mma.sync bf16 split-GEMM (proven R15 version).
// ---------------------------------------------------------------------------
__global__ void __launch_bounds__(256) out_mma_kernel(
    const float* __restrict__ Wr,
    const float* __restrict__ br,
    float* __restrict__ out,
    int n)
{
    __shared__ uint2 sBhi[2048];
    __shared__ uint2 sBlo[2048];

    int tid  = threadIdx.x;
    int lane = tid & 31;
    int w    = tid >> 5;
    int tg   = lane & 3;
    int g    = lane >> 2;

    for (int e = tid; e < 2048; e += 256) {
        int ln = e & 31;
        int kt = (e >> 5) & 7;
        int nt = e >> 8;
        int etg = ln & 3;
        int eg  = ln >> 2;
        int nrow = nt * 8 + eg;
        int k0 = kt * 16 + 2 * etg;
        float2 v0 = *reinterpret_cast<const float2*>(Wr + nrow * TWO_D + k0);
        float2 v1 = *reinterpret_cast<const float2*>(Wr + nrow * TWO_D + k0 + 8);
        uint32_t h0, l0, h1, l1;
        split2(v0.x, v0.y, h0, l0);
        split2(v1.x, v1.y, h1, l1);
        sBhi[e] = make_uint2(h0, h1);
        sBlo[e] = make_uint2(l0, l1);
    }
    __syncthreads();

    int m0 = blockIdx.x * 128 + w * 16;
    int r0 = m0 + g;
    int r1 = m0 + g + 8;
    bool p0 = r0 < n;
    bool p1 = r1 < n;

    float acc[8][4];
    #pragma unroll
    for (int nt = 0; nt < 8; nt++)
        #pragma unroll
        for (int q = 0; q < 4; q++)
            acc[nt][q] = 0.f;

    const float2* z2 = reinterpret_cast<const float2*>(g_z);
    const float2 zero2 = make_float2(0.f, 0.f);

    #pragma unroll
    for (int kt = 0; kt < 8; kt++) {
        int k0 = kt * 16 + 2 * tg;
        float2 v00 = p0 ? z2[(size_t)r0 * 64 + (k0 >> 1)]     : zero2;
        float2 v01 = p0 ? z2[(size_t)r0 * 64 + (k0 >> 1) + 4] : zero2;
        float2 v10 = p1 ? z2[(size_t)r1 * 64 + (k0 >> 1)]     : zero2;
        float2 v11 = p1 ? z2[(size_t)r1 * 64 + (k0 >> 1) + 4] : zero2;

        uint32_t a0h, a0l, a1h, a1l, a2h, a2l, a3h, a3l;
        split2(v00.x, v00.y, a0h, a0l);
        split2(v10.x, v10.y, a1h, a1l);
        split2(v01.x, v01.y, a2h, a2l);
        split2(v11.x, v11.y, a3h, a3l);

        #pragma unroll
        for (int nt = 0; nt < 8; nt++) {
            uint2 bh = sBhi[nt * 256 + kt * 32 + lane];
            uint2 bl = sBlo[nt * 256 + kt * 32 + lane];
            MMA_BF16(acc[nt], a0h, a1h, a2h, a3h, bh.x, bh.y);
            MMA_BF16(acc[nt], a0h, a1h, a2h, a3h, bl.x, bl.y);
            MMA_BF16(acc[nt], a0l, a1l, a2l, a3l, bh.x, bh.y);
        }
    }

    #pragma unroll
    for (int nt = 0; nt < 8; nt++) {
        int c0 = nt * 8 + 2 * tg;
        float2 b2 = *reinterpret_cast<const float2*>(br + c0);
        if (p0) {
            float2 o = make_float2(acc[nt][0] + b2.x, acc[nt][1] + b2.y);
            *reinterpret_cast<float2*>(out + (size_t)r0 * D + c0) = o;
        }
        if (p1) {
            float2 o = make_float2(acc[nt][2] + b2.x, acc[nt][3] + b2.y);
            *reinterpret_cast<float2*>(out + (size_t)r1 * D + c0) = o;
        }
    }
}

// ---------------------------------------------------------------------------
extern "C" void kernel_launch(void* const* d_in, const int* in_sizes, int n_in,
                              void* d_out, int out_size)
{
    const float* h   = (const float*)d_in[0];
    const float* dn  = (const float*)d_in[1];
    const int*   src = (const int*)  d_in[2];
    const int*   dst = (const int*)  d_in[3];
    const float* Wl  = (const float*)d_in[4];
    const float* bl  = (const float*)d_in[5];
    const float* Wh  = (const float*)d_in[6];
    const float* bh  = (const float*)d_in[7];
    const float* Wr  = (const float*)d_in[8];
    const float* br  = (const float*)d_in[9];
    float* out = (float*)d_out;

    int n = in_sizes[0] / D;      // nodes
    int e = in_sizes[2];          // edges
    int nb = (n + SCAN_B - 1) / SCAN_B;

    gate_kernel<<<(n * 32 + 255) / 256, 256>>>(h, dn, Wl, Wh, n);

    hist_kernel<<<((e >> 2) + 255) / 256, 256>>>(dst, e);
    scan1_kernel<<<nb, SCAN_B>>>(n);
    scan3_kernel<<<(n + 255) / 256, 256>>>(n, nb);
    fill_kernel<<<(e + 255) / 256, 256>>>(src, dst, e);

    // gather v3: two nodes per warp
    int gwarps = (n + 1) / 2;
    gather_kernel<<<(int)(((size_t)gwarps * 32 + 255) / 256), 256>>>(h, bl, bh, n);

    out_mma_kernel<<<(n + 127) / 128, 256>>>(Wr, br, out, n);
}